// round 2
// baseline (speedup 1.0000x reference)
#include <cuda_runtime.h>

#define NVERTS 2000000
#define NFACES 4000000
#define NITERS 10
#define DT 1e-8f
#define BULK 2500.0f
#define M21 ((1ull<<21)-1ull)

// Scratch (device globals: allocation-free per harness rules)
__device__ float4 g_x[2][NVERTS];                 // double-buffered padded vertices (64 MB)
__device__ unsigned long long g_fp[NFACES];       // packed 3x21-bit indices (32 MB)
__device__ double g_vol;
__device__ float g_p;
__device__ unsigned int g_cnt;

__device__ __forceinline__ void red4(float4* p, float x, float y, float z) {
    asm volatile("red.global.add.v4.f32 [%0], {%1, %2, %3, %4};"
                 :: "l"(p), "f"(x), "f"(y), "f"(z), "f"(0.0f) : "memory");
}

// Pass 0: pack faces to u64 (auto-detecting int32 vs int64 faces),
// seed x[0] from input, reset accumulators.
__global__ void __launch_bounds__(256) k_init(const float* __restrict__ v,
                                              const void* __restrict__ fraw) {
    int i = blockIdx.x * 256 + threadIdx.x;

    // dtype probe: true int64 indices are all < NVERTS; int32 data read as
    // int64 gives values >= 2^32 (high half = next random index, ~never 0).
    const long long* f64 = (const long long*)fraw;
    const int* f32 = (const int*)fraw;
    bool is64 = true;
    #pragma unroll
    for (int k = 0; k < 8; k++)
        if ((unsigned long long)__ldg(&f64[k]) >= (unsigned long long)NVERTS) is64 = false;

    if (i < NFACES) {
        unsigned long long a, b, c;
        if (is64) {
            a = (unsigned long long)__ldg(&f64[3*i+0]);
            b = (unsigned long long)__ldg(&f64[3*i+1]);
            c = (unsigned long long)__ldg(&f64[3*i+2]);
        } else {
            a = (unsigned long long)(unsigned int)__ldg(&f32[3*i+0]);
            b = (unsigned long long)(unsigned int)__ldg(&f32[3*i+1]);
            c = (unsigned long long)(unsigned int)__ldg(&f32[3*i+2]);
        }
        g_fp[i] = a | (b << 21) | (c << 42);
    }
    if (i < NVERTS) {
        g_x[0][i] = make_float4(v[3*i], v[3*i+1], v[3*i+2], 0.0f);
    }
    if (i == 0) { g_vol = 0.0; g_cnt = 0u; }
}

// Per iteration, pass 1: copy x -> x', reduce vol, last block computes p.
__global__ void __launch_bounds__(256) k_vol(int src) {
    int i = blockIdx.x * 256 + threadIdx.x;          // grid exactly covers NFACES
    const float4* __restrict__ xs = g_x[src];
    float4* __restrict__ xd = g_x[src ^ 1];
    if (i < NVERTS) xd[i] = __ldg(&xs[i]);           // double-buffer copy (fused)

    unsigned long long f = __ldcs(&g_fp[i]);
    int i0 = (int)(f & M21), i1 = (int)((f >> 21) & M21), i2 = (int)(f >> 42);
    float4 a = __ldg(&xs[i0]);
    float4 b = __ldg(&xs[i1]);
    float4 c = __ldg(&xs[i2]);
    float det = a.x * (b.y * c.z - b.z * c.y)
              + a.y * (b.z * c.x - b.x * c.z)
              + a.z * (b.x * c.y - b.y * c.x);
    #pragma unroll
    for (int o = 16; o > 0; o >>= 1) det += __shfl_down_sync(0xffffffffu, det, o);

    __shared__ float ws[8];
    if ((threadIdx.x & 31) == 0) ws[threadIdx.x >> 5] = det;
    __syncthreads();
    if (threadIdx.x == 0) {
        double s = 0.0;
        #pragma unroll
        for (int k = 0; k < 8; k++) s += (double)ws[k];
        atomicAdd(&g_vol, s);
        __threadfence();
        unsigned t = atomicInc(&g_cnt, gridDim.x - 1u);   // wraps to 0 on last
        if (t == gridDim.x - 1u) {
            double vol = atomicAdd(&g_vol, 0.0) * (1.0 / 6.0);
            float stv = expf(0.04f);                      // exp(PRESSURE0/BULK)
            g_p = BULK * (stv - (float)vol) / stv;
            g_vol = 0.0;                                  // ready for next iter
        }
    }
}

// Per iteration, pass 2: per-face forces, dt-scaled, atomically into x'.
__global__ void __launch_bounds__(256) k_force(int src) {
    int i = blockIdx.x * 256 + threadIdx.x;
    const float4* __restrict__ xs = g_x[src];
    float4* xd = g_x[src ^ 1];

    unsigned long long f = __ldcs(&g_fp[i]);
    int i0 = (int)(f & M21), i1 = (int)((f >> 21) & M21), i2 = (int)(f >> 42);
    float4 a = __ldg(&xs[i0]);
    float4 b = __ldg(&xs[i1]);
    float4 c = __ldg(&xs[i2]);

    float p = g_p;
    float q = p * (DT / 6.0f);       // dt * p * dV,  dV = cross/6
    const float s = 0.5f * DT;       // dt * SURFACE_TENSION * 0.5

    // n = cross(b-a, c-a); n_hat = n / (|n| + 1e-12)
    float e1x = b.x - a.x, e1y = b.y - a.y, e1z = b.z - a.z;
    float e2x = c.x - a.x, e2y = c.y - a.y, e2z = c.z - a.z;
    float nx = e1y * e2z - e1z * e2y;
    float ny = e1z * e2x - e1x * e2z;
    float nz = e1x * e2y - e1y * e2x;
    float inv = 1.0f / (sqrtf(nx*nx + ny*ny + nz*nz) + 1e-12f);
    float hx = nx * inv, hy = ny * inv, hz = nz * inv;

    // g0 = q*cross(b,c) - s*cross(h, c-b)
    float d0x = c.x - b.x, d0y = c.y - b.y, d0z = c.z - b.z;
    float g0x = q * (b.y*c.z - b.z*c.y) - s * (hy*d0z - hz*d0y);
    float g0y = q * (b.z*c.x - b.x*c.z) - s * (hz*d0x - hx*d0z);
    float g0z = q * (b.x*c.y - b.y*c.x) - s * (hx*d0y - hy*d0x);
    // g1 = q*cross(c,a) - s*cross(h, a-c)
    float d1x = a.x - c.x, d1y = a.y - c.y, d1z = a.z - c.z;
    float g1x = q * (c.y*a.z - c.z*a.y) - s * (hy*d1z - hz*d1y);
    float g1y = q * (c.z*a.x - c.x*a.z) - s * (hz*d1x - hx*d1z);
    float g1z = q * (c.x*a.y - c.y*a.x) - s * (hx*d1y - hy*d1x);
    // g2 = q*cross(a,b) - s*cross(h, b-a)
    float g2x = q * (a.y*b.z - a.z*b.y) - s * (hy*e1z - hz*e1y);
    float g2y = q * (a.z*b.x - a.x*b.z) - s * (hz*e1x - hx*e1z);
    float g2z = q * (a.x*b.y - a.y*b.x) - s * (hx*e1y - hy*e1x);

    red4(&xd[i0], g0x, g0y, g0z);
    red4(&xd[i1], g1x, g1y, g1z);
    red4(&xd[i2], g2x, g2y, g2z);
}

// Final: unpad into d_out.
__global__ void __launch_bounds__(256) k_pack(float* __restrict__ out, int src) {
    int i = blockIdx.x * 256 + threadIdx.x;
    if (i < NVERTS) {
        float4 v = g_x[src][i];
        out[3*i] = v.x; out[3*i+1] = v.y; out[3*i+2] = v.z;
    }
}

extern "C" void kernel_launch(void* const* d_in, const int* in_sizes, int n_in,
                              void* d_out, int out_size) {
    // Identify inputs by element count: vertices = 6M floats, faces = 12M ints.
    const float* verts;
    const void* faces;
    if (in_sizes[0] == 3 * NVERTS) {
        verts = (const float*)d_in[0];
        faces = d_in[1];
    } else {
        verts = (const float*)d_in[1];
        faces = d_in[0];
    }
    const int FB = NFACES / 256;                   // 15625, exact cover

    k_init<<<FB, 256>>>(verts, faces);
    int src = 0;
    for (int it = 0; it < NITERS; it++) {
        k_vol<<<FB, 256>>>(src);
        k_force<<<FB, 256>>>(src);
        src ^= 1;
    }
    k_pack<<<(NVERTS + 255) / 256, 256>>>((float*)d_out, src);
}